// round 14
// baseline (speedup 1.0000x reference)
#include <cuda_runtime.h>
#include <math.h>
#include <float.h>

#define B   16
#define N   32768
#define DIM 256
#define S   64
#define NS  8

#define FPS_CTAS   8            // CTAs per batch (cluster size)
#define FPS_THR    512          // threads per CTA
#define PPT        8            // points per thread (4096 / 512)

// ---------------- scratch (static device globals; no allocation) ----------------
__device__ float4 g_coor4[B * N];            // packed coords — 8MB (written by k_fps)
__device__ int    g_fps[B * S];
__device__ float  g_nq[B * S * DIM];
__device__ float  g_nk[B * S * DIM];
__device__ float  g_m[DIM * DIM];            // Mt[e][d] = sum_c Wk[c,e] Wq[c,d]
__device__ float  g_qmp[4][B * S * DIM];     // split-K partials of nq @ Mt^T
__device__ float  g_lsp[4][B * S * S];       // split-K partial logits
__device__ float  g_dc[B * S * 3];
__device__ float  g_dif[B * S * 3];
__device__ float  g_sc[B * S * 3];
__device__ float  g_sif[B * S * 3];

// ---------------- cluster helpers ----------------
__device__ __forceinline__ unsigned cl_rank() {
    unsigned r; asm("mov.u32 %0, %%cluster_ctarank;" : "=r"(r)); return r;
}
__device__ __forceinline__ void cl_sync() {
    asm volatile("barrier.cluster.arrive.aligned;" ::: "memory");
    asm volatile("barrier.cluster.wait.aligned;"   ::: "memory");
}
__device__ __forceinline__ unsigned smem_u32(const void* p) {
    unsigned a;
    asm("{ .reg .u64 t; cvta.to.shared.u64 t, %1; cvt.u32.u64 %0, t; }" : "=r"(a) : "l"(p));
    return a;
}
__device__ __forceinline__ unsigned mapa_u32(unsigned saddr, unsigned rank) {
    unsigned rem;
    asm volatile("mapa.shared::cluster.u32 %0, %1, %2;" : "=r"(rem) : "r"(saddr), "r"(rank));
    return rem;
}
__device__ __forceinline__ void st_cl_u64(unsigned addr, unsigned long long v) {
    asm volatile("st.shared::cluster.b64 [%0], %1;" :: "r"(addr), "l"(v) : "memory");
}

// pack (dist, idx) so u64-max == (max dist, tie -> min idx). dist >= 0.
__device__ __forceinline__ unsigned long long pack_cand(float v, int idx) {
    return ((unsigned long long)__float_as_uint(v) << 32) |
           (unsigned long long)(0xFFFFFFFFu - (unsigned)idx);
}

// ---------------- K1: FPS (pack fused) — cluster of 8 CTAs, cluster.sync exchange --
// Payload: s_ex[buf][rank] = {key, packed(x,y), z}; remote stores at fixed
// +0/+8/+16 from the slot base (layout-safe). cluster.arrive=release /
// cluster.wait=acquire orders all remote stores, and subsumes __syncthreads for
// intra-CTA reuse of s_wk. Double buffer: same-buffer writes of step s+2 are
// behind the s+1 barrier, behind all step-s reads.
// 512 thr x 8 pts: shorter per-warp chains + 4 warps/SMSP for latency hiding.
__global__ void __launch_bounds__(FPS_THR, 1) __cluster_dims__(FPS_CTAS, 1, 1)
k_fps(const float* __restrict__ coor) {
    int b = blockIdx.x / FPS_CTAS;
    unsigned rank = cl_rank();
    int t = threadIdx.x;
    int base = rank * (N / FPS_CTAS);
    const float* __restrict__ cb = coor + (size_t)b * N * 3;

    float px[PPT], py[PPT], pz[PPT], dists[PPT];
#pragma unroll
    for (int k = 0; k < PPT; k++) {
        int p = base + t + k * FPS_THR;
        float x = cb[3 * p + 0];
        float y = cb[3 * p + 1];
        float z = cb[3 * p + 2];
        px[k] = x; py[k] = y; pz[k] = z;
        dists[k] = 1e10f;
        float4 v; v.x = x; v.y = y; v.z = z; v.w = 0.f;
        g_coor4[b * N + p] = v;
    }

    __shared__ unsigned long long s_ex[2][FPS_CTAS][3];   // key, xy, z
    __shared__ unsigned long long s_wk[FPS_THR / 32];
    __shared__ float s_wx[FPS_THR / 32], s_wy[FPS_THR / 32], s_wz[FPS_THR / 32];

    if (rank == 0 && t == 0) g_fps[b * S] = 0;

    float lx = cb[0], ly = cb[1], lz = cb[2];

    unsigned loc_b0 = smem_u32(&s_ex[0][rank][0]);
    unsigned loc_b1 = smem_u32(&s_ex[1][rank][0]);

    for (int step = 1; step < S; step++) {
        int buf = step & 1;
        float best = -1.0f;
#pragma unroll
        for (int k = 0; k < PPT; k++) {
            float dx = px[k] - lx, dy = py[k] - ly, dz = pz[k] - lz;
            float d = __fadd_rn(__fadd_rn(__fmul_rn(dx, dx), __fmul_rn(dy, dy)),
                                __fmul_rn(dz, dz));
            float nd = fminf(dists[k], d);
            dists[k] = nd;
            best = fmaxf(best, nd);
        }
        // resolve: descending k, unconditional overwrite => lowest idx on ties
        int besti = base + t;
        float bx = px[0], by = py[0], bz = pz[0];
#pragma unroll
        for (int k = PPT - 1; k >= 0; k--) {
            if (dists[k] == best) {
                besti = base + t + k * FPS_THR;
                bx = px[k]; by = py[k]; bz = pz[k];
            }
        }
        unsigned long long key = pack_cand(best, besti);

        // warp stage: butterfly max on key; unique winner lane writes
        unsigned long long wkey = key;
#pragma unroll
        for (int o = 16; o; o >>= 1) {
            unsigned long long ok = __shfl_xor_sync(0xffffffffu, wkey, o);
            if (ok > wkey) wkey = ok;
        }
        if (key == wkey) {
            int w = t >> 5;
            s_wk[w] = wkey; s_wx[w] = bx; s_wy[w] = by; s_wz[w] = bz;
        }
        __syncthreads();

        // block stage: threads t<8 each scan the warp winners; thread t ships to CTA t
        if (t < FPS_CTAS) {
            unsigned long long k0 = s_wk[0]; int ws = 0;
#pragma unroll
            for (int w = 1; w < FPS_THR / 32; w++) {
                unsigned long long v = s_wk[w];
                if (v > k0) { k0 = v; ws = w; }
            }
            float wx = s_wx[ws], wy = s_wy[ws], wz = s_wz[ws];
            unsigned long long xy = ((unsigned long long)__float_as_uint(wy) << 32) |
                                    (unsigned long long)__float_as_uint(wx);
            unsigned long long zz = (unsigned long long)__float_as_uint(wz);
            unsigned loc = buf ? loc_b1 : loc_b0;
            unsigned pbase = mapa_u32(loc, t);
            st_cl_u64(pbase,      k0);
            st_cl_u64(pbase + 8,  xy);
            st_cl_u64(pbase + 16, zz);
        }
        cl_sync();   // release all 8 CTAs' stores, acquire everyone's

        // every thread redundantly picks the winner from local smem
        unsigned long long wmax = s_ex[buf][0][0];
        int w = 0;
#pragma unroll
        for (int c = 1; c < FPS_CTAS; c++) {
            unsigned long long v = s_ex[buf][c][0];
            if (v > wmax) { wmax = v; w = c; }
        }
        unsigned long long xy = s_ex[buf][w][1];
        lx = __uint_as_float((unsigned)(xy & 0xFFFFFFFFull));
        ly = __uint_as_float((unsigned)(xy >> 32));
        lz = __uint_as_float((unsigned)(s_ex[buf][w][2] & 0xFFFFFFFFull));
        if (rank == 0 && t == 0)
            g_fps[b * S + step] = (int)(0xFFFFFFFFu - (unsigned)(wmax & 0xFFFFFFFFull));
    }
    cl_sync();   // no CTA exits while peers may still address its smem
}

// ---------------- K2: ball query + gather + max + LayerNorms + out0 ----------------
__global__ void __launch_bounds__(256) k_group(
    const float* __restrict__ x, const float* __restrict__ iff,
    const float* __restrict__ gq, const float* __restrict__ bq,
    const float* __restrict__ gk, const float* __restrict__ bk,
    float* __restrict__ out0)
{
    int blk = blockIdx.x;
    int b = blk >> 6, s = blk & 63;
    int tid = threadIdx.x;

    __shared__ int   s_nidx[NS];
    __shared__ int   s_sidx;
    __shared__ float s_cx, s_cy, s_cz;
    __shared__ float s_red[32];
    __shared__ float s_stats[4];

    if (tid == 0) {
        int si = g_fps[b * S + s];
        s_sidx = si;
        float4 c = g_coor4[b * N + si];
        s_cx = c.x; s_cy = c.y; s_cz = c.z;
    }
    __syncthreads();

    if (tid < 32) {
        int lane = tid;
        float cx = s_cx, cy = s_cy, cz = s_cz;
        const float4* __restrict__ cp = g_coor4 + b * N;
        int found = 0;
        for (int base = 0; base < N && found < NS; base += 32) {
            float4 c = cp[base + lane];
            float dx = cx - c.x, dy = cy - c.y, dz = cz - c.z;
            float d2 = __fadd_rn(__fadd_rn(__fmul_rn(dx, dx), __fmul_rn(dy, dy)),
                                 __fmul_rn(dz, dz));
            bool v = d2 < 16.0f;
            unsigned m = __ballot_sync(0xffffffffu, v);
            int take = min(NS - found, __popc(m));
            int rank = __popc(m & ((1u << lane) - 1u));
            if (v && rank < take) s_nidx[found + rank] = base + lane;
            found += take;
        }
        __syncwarp();
        if (lane == 0) {
            int f0 = s_nidx[0];
            for (int j = found; j < NS; j++) s_nidx[j] = f0;
        }
    }
    __syncthreads();

    int c = tid;
    const float* __restrict__ xb = x + (size_t)b * N * DIM;
    int sidx = s_sidx;
    float sx = xb[(size_t)sidx * DIM + c];
    float gx = -FLT_MAX;
    int nidx[NS];
#pragma unroll
    for (int j = 0; j < NS; j++) nidx[j] = s_nidx[j];
#pragma unroll
    for (int j = 0; j < NS; j++)
        gx = fmaxf(gx, xb[(size_t)nidx[j] * DIM + c]);

    float x2 = gx - sx;
    out0[(size_t)(b * S + s) * DIM + c] = sx + x2;

    float v0 = sx, v1 = sx * sx, v2 = x2, v3 = x2 * x2;
#pragma unroll
    for (int o = 16; o; o >>= 1) {
        v0 += __shfl_down_sync(0xffffffffu, v0, o);
        v1 += __shfl_down_sync(0xffffffffu, v1, o);
        v2 += __shfl_down_sync(0xffffffffu, v2, o);
        v3 += __shfl_down_sync(0xffffffffu, v3, o);
    }
    int wid = tid >> 5;
    if ((tid & 31) == 0) {
        s_red[wid]      = v0;
        s_red[8 + wid]  = v1;
        s_red[16 + wid] = v2;
        s_red[24 + wid] = v3;
    }
    __syncthreads();
    if (tid == 0) {
        float t0 = 0, t1 = 0, t2 = 0, t3 = 0;
#pragma unroll
        for (int i = 0; i < 8; i++) {
            t0 += s_red[i]; t1 += s_red[8 + i]; t2 += s_red[16 + i]; t3 += s_red[24 + i];
        }
        float mk = t0 * (1.0f / DIM);
        float vk = t1 * (1.0f / DIM) - mk * mk;
        float mq = t2 * (1.0f / DIM);
        float vq = t3 * (1.0f / DIM) - mq * mq;
        s_stats[0] = mk;
        s_stats[1] = rsqrtf(vk + 1e-5f);
        s_stats[2] = mq;
        s_stats[3] = rsqrtf(vq + 1e-5f);
    }
    __syncthreads();

    float nk = (sx - s_stats[0]) * s_stats[1] * gk[c] + bk[c];
    float nq = (x2 - s_stats[2]) * s_stats[3] * gq[c] + bq[c];
    g_nk[(b * S + s) * DIM + c] = nk;
    g_nq[(b * S + s) * DIM + c] = nq;

    if (tid < 3) {
        float cen = (tid == 0) ? s_cx : (tid == 1) ? s_cy : s_cz;
        float acc = 0.f, acci = 0.f;
#pragma unroll
        for (int j = 0; j < NS; j++) {
            int p = nidx[j];
            float4 c4 = g_coor4[b * N + p];
            float comp = (tid == 0) ? c4.x : (tid == 1) ? c4.y : c4.z;
            acc  += (comp - cen);
            acci += iff[((size_t)b * N + p) * 3 + tid];
        }
        int o = (b * S + s) * 3 + tid;
        g_dc[o]  = acc * 0.125f;
        g_dif[o] = acci * 0.125f;
        g_sc[o]  = cen;
        g_sif[o] = iff[((size_t)b * N + sidx) * 3 + tid];
    }
}

// ---------------- K3a: Mt[e,d] = sum_c Wk[c,e] * Wq[c,d]  (256x256x256) ----------
__global__ void __launch_bounds__(256) k_wm(const float* __restrict__ Wq,
                                            const float* __restrict__ Wk)
{
    __shared__ float As[32][68];   // Wq chunk [cc][dd]
    __shared__ float Bs[32][68];   // Wk chunk [cc][ee]
    int tid = threadIdx.x;
    int d0 = blockIdx.x * 64;
    int e0 = blockIdx.y * 64;
    int tr = tid >> 4, tc = tid & 15;

    float acc[4][4] = {};
    for (int c0 = 0; c0 < 256; c0 += 32) {
        __syncthreads();
#pragma unroll
        for (int l = 0; l < 2; l++) {
            int idx = tid + l * 256;
            int cc = idx >> 4;
            int dq = idx & 15;
            *(float4*)&As[cc][dq * 4] = *(const float4*)&Wq[(c0 + cc) * 256 + d0 + dq * 4];
            *(float4*)&Bs[cc][dq * 4] = *(const float4*)&Wk[(c0 + cc) * 256 + e0 + dq * 4];
        }
        __syncthreads();
#pragma unroll
        for (int kk = 0; kk < 32; kk++) {
            float4 a4 = *(float4*)&Bs[kk][tr * 4];   // e
            float4 b4 = *(float4*)&As[kk][tc * 4];   // d
            float av[4] = {a4.x, a4.y, a4.z, a4.w};
            float bv[4] = {b4.x, b4.y, b4.z, b4.w};
#pragma unroll
            for (int i = 0; i < 4; i++)
#pragma unroll
                for (int j = 0; j < 4; j++)
                    acc[i][j] += av[i] * bv[j];
        }
    }
#pragma unroll
    for (int i = 0; i < 4; i++)
#pragma unroll
        for (int j = 0; j < 4; j++)
            g_m[(e0 + tr * 4 + i) * 256 + d0 + tc * 4 + j] = acc[i][j];
}

// ---------------- K3b: qm = nq @ Mt^T, split-K=4, 64x64 tiles, reg-prefetch --------
__global__ void __launch_bounds__(256) k_gemm() {
    int ks = blockIdx.z;                     // 0..3
    const float* __restrict__ A = g_nq;
    const float* __restrict__ W = g_m;       // Mt rows = e
    float* __restrict__ O = g_qmp[ks];

    __shared__ float As[32][68];
    __shared__ float Bs[32][68];
    int tid = threadIdx.x;
    int row0 = blockIdx.x * 64;
    int col0 = blockIdx.y * 64;
    int tr = tid >> 4, tc = tid & 15;
    int kbase = ks * 64;

    int r0 = tid >> 3, kq0 = tid & 7;
    int r1 = r0 + 32;

    float4 fa[2], fb[2];
    fa[0] = *(const float4*)&A[(size_t)(row0 + r0) * 256 + kbase + kq0 * 4];
    fb[0] = *(const float4*)&W[(size_t)(col0 + r0) * 256 + kbase + kq0 * 4];
    fa[1] = *(const float4*)&A[(size_t)(row0 + r1) * 256 + kbase + kq0 * 4];
    fb[1] = *(const float4*)&W[(size_t)(col0 + r1) * 256 + kbase + kq0 * 4];

    float acc[4][4] = {};
#pragma unroll
    for (int kt = 0; kt < 2; kt++) {
        As[kq0 * 4 + 0][r0] = fa[0].x; As[kq0 * 4 + 1][r0] = fa[0].y;
        As[kq0 * 4 + 2][r0] = fa[0].z; As[kq0 * 4 + 3][r0] = fa[0].w;
        Bs[kq0 * 4 + 0][r0] = fb[0].x; Bs[kq0 * 4 + 1][r0] = fb[0].y;
        Bs[kq0 * 4 + 2][r0] = fb[0].z; Bs[kq0 * 4 + 3][r0] = fb[0].w;
        As[kq0 * 4 + 0][r1] = fa[1].x; As[kq0 * 4 + 1][r1] = fa[1].y;
        As[kq0 * 4 + 2][r1] = fa[1].z; As[kq0 * 4 + 3][r1] = fa[1].w;
        Bs[kq0 * 4 + 0][r1] = fb[1].x; Bs[kq0 * 4 + 1][r1] = fb[1].y;
        Bs[kq0 * 4 + 2][r1] = fb[1].z; Bs[kq0 * 4 + 3][r1] = fb[1].w;
        __syncthreads();
        if (kt < 1) {
            int ko = kbase + 32;
            fa[0] = *(const float4*)&A[(size_t)(row0 + r0) * 256 + ko + kq0 * 4];
            fb[0] = *(const float4*)&W[(size_t)(col0 + r0) * 256 + ko + kq0 * 4];
            fa[1] = *(const float4*)&A[(size_t)(row0 + r1) * 256 + ko + kq0 * 4];
            fb[1] = *(const float4*)&W[(size_t)(col0 + r1) * 256 + ko + kq0 * 4];
        }
#pragma unroll
        for (int kk = 0; kk < 32; kk++) {
            float4 a4 = *(float4*)&As[kk][tr * 4];
            float4 b4 = *(float4*)&Bs[kk][tc * 4];
            float av[4] = {a4.x, a4.y, a4.z, a4.w};
            float bv[4] = {b4.x, b4.y, b4.z, b4.w};
#pragma unroll
            for (int i = 0; i < 4; i++)
#pragma unroll
                for (int j = 0; j < 4; j++)
                    acc[i][j] += av[i] * bv[j];
        }
        __syncthreads();
    }
#pragma unroll
    for (int i = 0; i < 4; i++)
#pragma unroll
        for (int j = 0; j < 4; j++)
            O[(size_t)(row0 + tr * 4 + i) * 256 + col0 + tc * 4 + j] = acc[i][j];
}

// ---------------- K4a: logits partials = qm @ nk^T (split-K=4 over e) -------------
__global__ void __launch_bounds__(256) k_logits() {
    int b = blockIdx.x, ks = blockIdx.y;
    int kbase = ks * 64;

    __shared__ float As[32][68];
    __shared__ float Bs[32][68];
    int tid = threadIdx.x;
    int tr = tid >> 4, tc = tid & 15;
    int r0 = tid >> 3, kq0 = tid & 7;
    int r1 = r0 + 32;

    float acc[4][4] = {};
#pragma unroll
    for (int kt = 0; kt < 2; kt++) {
        int ko = kbase + kt * 32;
        size_t off0 = (size_t)(b * 64 + r0) * 256 + ko + kq0 * 4;
        size_t off1 = (size_t)(b * 64 + r1) * 256 + ko + kq0 * 4;
        float4 q0 = *(const float4*)&g_qmp[0][off0], q1 = *(const float4*)&g_qmp[1][off0];
        float4 q2 = *(const float4*)&g_qmp[2][off0], q3 = *(const float4*)&g_qmp[3][off0];
        float4 u0 = *(const float4*)&g_qmp[0][off1], u1 = *(const float4*)&g_qmp[1][off1];
        float4 u2 = *(const float4*)&g_qmp[2][off1], u3 = *(const float4*)&g_qmp[3][off1];
        float4 n0 = *(const float4*)&g_nk[off0];
        float4 n1 = *(const float4*)&g_nk[off1];
        float4 a0, a1;
        a0.x = (q0.x + q1.x) + (q2.x + q3.x); a0.y = (q0.y + q1.y) + (q2.y + q3.y);
        a0.z = (q0.z + q1.z) + (q2.z + q3.z); a0.w = (q0.w + q1.w) + (q2.w + q3.w);
        a1.x = (u0.x + u1.x) + (u2.x + u3.x); a1.y = (u0.y + u1.y) + (u2.y + u3.y);
        a1.z = (u0.z + u1.z) + (u2.z + u3.z); a1.w = (u0.w + u1.w) + (u2.w + u3.w);
        __syncthreads();
        As[kq0 * 4 + 0][r0] = a0.x; As[kq0 * 4 + 1][r0] = a0.y;
        As[kq0 * 4 + 2][r0] = a0.z; As[kq0 * 4 + 3][r0] = a0.w;
        Bs[kq0 * 4 + 0][r0] = n0.x; Bs[kq0 * 4 + 1][r0] = n0.y;
        Bs[kq0 * 4 + 2][r0] = n0.z; Bs[kq0 * 4 + 3][r0] = n0.w;
        As[kq0 * 4 + 0][r1] = a1.x; As[kq0 * 4 + 1][r1] = a1.y;
        As[kq0 * 4 + 2][r1] = a1.z; As[kq0 * 4 + 3][r1] = a1.w;
        Bs[kq0 * 4 + 0][r1] = n1.x; Bs[kq0 * 4 + 1][r1] = n1.y;
        Bs[kq0 * 4 + 2][r1] = n1.z; Bs[kq0 * 4 + 3][r1] = n1.w;
        __syncthreads();
#pragma unroll
        for (int kk = 0; kk < 32; kk++) {
            float4 a4 = *(float4*)&As[kk][tr * 4];
            float4 b4 = *(float4*)&Bs[kk][tc * 4];
            float av[4] = {a4.x, a4.y, a4.z, a4.w};
            float bv[4] = {b4.x, b4.y, b4.z, b4.w};
#pragma unroll
            for (int i = 0; i < 4; i++)
#pragma unroll
                for (int j = 0; j < 4; j++)
                    acc[i][j] += av[i] * bv[j];
        }
    }
    float* __restrict__ O = g_lsp[ks] + b * S * S;
#pragma unroll
    for (int i = 0; i < 4; i++)
#pragma unroll
        for (int j = 0; j < 4; j++)
            O[(tr * 4 + i) * S + tc * 4 + j] = acc[i][j];
}

// ---------------- K4b: sum partial logits + softmax + attn@v + residuals ----------------
__global__ void __launch_bounds__(192) k_out(float* __restrict__ out) {
    int b = blockIdx.x;
    int tid = threadIdx.x;
    __shared__ float vc[192];
    __shared__ float vi[192];

    if (tid < 192) {
        int l = tid;
        int src = b * 192 + (l & 63) * 3 + (l >> 6);
        vc[tid] = g_dc[src];
        vi[tid] = g_dif[src];
    }
    __syncthreads();

    if (tid < S) {
        const float* __restrict__ l0 = g_lsp[0] + b * S * S + tid * S;
        const float* __restrict__ l1 = g_lsp[1] + b * S * S + tid * S;
        const float* __restrict__ l2 = g_lsp[2] + b * S * S + tid * S;
        const float* __restrict__ l3 = g_lsp[3] + b * S * S + tid * S;
        float lv[S];
        float mx = -FLT_MAX;
#pragma unroll
        for (int m = 0; m < S; m++) {
            lv[m] = (l0[m] + l1[m]) + (l2[m] + l3[m]);
            mx = fmaxf(mx, lv[m]);
        }
        float sum = 0.f;
        float a0 = 0, a1 = 0, a2 = 0, c0 = 0, c1 = 0, c2 = 0;
#pragma unroll
        for (int m = 0; m < S; m++) {
            float w = expf(lv[m] - mx);
            sum += w;
            a0 += w * vc[m * 3 + 0]; a1 += w * vc[m * 3 + 1]; a2 += w * vc[m * 3 + 2];
            c0 += w * vi[m * 3 + 0]; c1 += w * vi[m * 3 + 1]; c2 += w * vi[m * 3 + 2];
        }
        float inv = 1.0f / sum;
        int o = (b * S + tid) * 3;
        float* out1 = out + (size_t)B * S * DIM;
        float* out2 = out1 + B * S * 3;
        out1[o + 0] = g_sc[o + 0] + a0 * inv;
        out1[o + 1] = g_sc[o + 1] + a1 * inv;
        out1[o + 2] = g_sc[o + 2] + a2 * inv;
        out2[o + 0] = g_sif[o + 0] + c0 * inv;
        out2[o + 1] = g_sif[o + 1] + c1 * inv;
        out2[o + 2] = g_sif[o + 2] + c2 * inv;
    }
}

// ---------------- launch ----------------
extern "C" void kernel_launch(void* const* d_in, const int* in_sizes, int n_in,
                              void* d_out, int out_size)
{
    const float* iff  = (const float*)d_in[0];
    const float* x    = (const float*)d_in[1];
    const float* coor = (const float*)d_in[2];
    const float* Wq   = (const float*)d_in[3];
    const float* Wk   = (const float*)d_in[4];
    const float* gq   = (const float*)d_in[5];
    const float* bq   = (const float*)d_in[6];
    const float* gk   = (const float*)d_in[7];
    const float* bk   = (const float*)d_in[8];
    float* out = (float*)d_out;

    k_wm<<<dim3(4, 4), 256>>>(Wq, Wk);          // independent; overlaps FPS region
    k_fps<<<B * FPS_CTAS, FPS_THR>>>(coor);
    k_group<<<B * S, 256>>>(x, iff, gq, bq, gk, bk, out);
    k_gemm<<<dim3(16, 4, 4), 256>>>();
    k_logits<<<dim3(16, 4), 256>>>();
    k_out<<<B, 192>>>(out);
}

// round 15
// speedup vs baseline: 1.4571x; 1.4571x over previous
#include <cuda_runtime.h>
#include <math.h>
#include <float.h>

#define B   16
#define N   32768
#define DIM 256
#define S   64
#define NS  8

#define FPS_CTAS   8            // CTAs per batch (cluster size)
#define FPS_THR    256          // threads per CTA
#define PPT        16           // points per thread (4096 / 256)

// ---------------- scratch (static device globals; no allocation) ----------------
__device__ float4 g_coor4[B * N];            // packed coords — 8MB (written by k_fps)
__device__ int    g_fps[B * S];
__device__ float  g_nq[B * S * DIM];
__device__ float  g_nk[B * S * DIM];
__device__ float  g_m[DIM * DIM];            // Mt[e][d] = sum_c Wk[c,e] Wq[c,d]
__device__ float  g_lsp[4][B * S * S];       // split-e partial logits
__device__ float  g_dc[B * S * 3];
__device__ float  g_dif[B * S * 3];
__device__ float  g_sc[B * S * 3];
__device__ float  g_sif[B * S * 3];

// ---------------- cluster helpers ----------------
__device__ __forceinline__ unsigned cl_rank() {
    unsigned r; asm("mov.u32 %0, %%cluster_ctarank;" : "=r"(r)); return r;
}
__device__ __forceinline__ void cl_sync() {
    asm volatile("barrier.cluster.arrive.aligned;" ::: "memory");
    asm volatile("barrier.cluster.wait.aligned;"   ::: "memory");
}
__device__ __forceinline__ unsigned smem_u32(const void* p) {
    unsigned a;
    asm("{ .reg .u64 t; cvta.to.shared.u64 t, %1; cvt.u32.u64 %0, t; }" : "=r"(a) : "l"(p));
    return a;
}
__device__ __forceinline__ unsigned mapa_u32(unsigned saddr, unsigned rank) {
    unsigned rem;
    asm volatile("mapa.shared::cluster.u32 %0, %1, %2;" : "=r"(rem) : "r"(saddr), "r"(rank));
    return rem;
}
__device__ __forceinline__ void st_cl_u64(unsigned addr, unsigned long long v) {
    asm volatile("st.shared::cluster.b64 [%0], %1;" :: "r"(addr), "l"(v) : "memory");
}

// pack (dist, idx) so u64-max == (max dist, tie -> min idx). dist >= 0.
__device__ __forceinline__ unsigned long long pack_cand(float v, int idx) {
    return ((unsigned long long)__float_as_uint(v) << 32) |
           (unsigned long long)(0xFFFFFFFFu - (unsigned)idx);
}

// ---------------- K1: FPS (pack fused) — cluster of 8 CTAs, cluster.sync exchange --
// EXACT R12 configuration (256 thr x 16 ppt) — proven 131.8us; frozen.
__global__ void __launch_bounds__(FPS_THR, 1) __cluster_dims__(FPS_CTAS, 1, 1)
k_fps(const float* __restrict__ coor) {
    int b = blockIdx.x / FPS_CTAS;
    unsigned rank = cl_rank();
    int t = threadIdx.x;
    int base = rank * (N / FPS_CTAS);
    const float* __restrict__ cb = coor + (size_t)b * N * 3;

    float px[PPT], py[PPT], pz[PPT], dists[PPT];
#pragma unroll
    for (int k = 0; k < PPT; k++) {
        int p = base + t + k * FPS_THR;
        float x = cb[3 * p + 0];
        float y = cb[3 * p + 1];
        float z = cb[3 * p + 2];
        px[k] = x; py[k] = y; pz[k] = z;
        dists[k] = 1e10f;
        float4 v; v.x = x; v.y = y; v.z = z; v.w = 0.f;
        g_coor4[b * N + p] = v;
    }

    __shared__ unsigned long long s_ex[2][FPS_CTAS][3];   // key, xy, z
    __shared__ unsigned long long s_wk[FPS_THR / 32];
    __shared__ float s_wx[FPS_THR / 32], s_wy[FPS_THR / 32], s_wz[FPS_THR / 32];

    if (rank == 0 && t == 0) g_fps[b * S] = 0;

    float lx = cb[0], ly = cb[1], lz = cb[2];

    unsigned loc_b0 = smem_u32(&s_ex[0][rank][0]);
    unsigned loc_b1 = smem_u32(&s_ex[1][rank][0]);

    for (int step = 1; step < S; step++) {
        int buf = step & 1;
        float best = -1.0f;
#pragma unroll
        for (int k = 0; k < PPT; k++) {
            float dx = px[k] - lx, dy = py[k] - ly, dz = pz[k] - lz;
            float d = __fadd_rn(__fadd_rn(__fmul_rn(dx, dx), __fmul_rn(dy, dy)),
                                __fmul_rn(dz, dz));
            float nd = fminf(dists[k], d);
            dists[k] = nd;
            best = fmaxf(best, nd);
        }
        // resolve: descending k, unconditional overwrite => lowest idx on ties
        int besti = base + t;
        float bx = px[0], by = py[0], bz = pz[0];
#pragma unroll
        for (int k = PPT - 1; k >= 0; k--) {
            if (dists[k] == best) {
                besti = base + t + k * FPS_THR;
                bx = px[k]; by = py[k]; bz = pz[k];
            }
        }
        unsigned long long key = pack_cand(best, besti);

        // warp stage: butterfly max on key; unique winner lane writes
        unsigned long long wkey = key;
#pragma unroll
        for (int o = 16; o; o >>= 1) {
            unsigned long long ok = __shfl_xor_sync(0xffffffffu, wkey, o);
            if (ok > wkey) wkey = ok;
        }
        if (key == wkey) {
            int w = t >> 5;
            s_wk[w] = wkey; s_wx[w] = bx; s_wy[w] = by; s_wz[w] = bz;
        }
        __syncthreads();

        // block stage: threads t<8 each scan the warp winners; thread t ships to CTA t
        if (t < FPS_CTAS) {
            unsigned long long k0 = s_wk[0]; int ws = 0;
#pragma unroll
            for (int w = 1; w < FPS_THR / 32; w++) {
                unsigned long long v = s_wk[w];
                if (v > k0) { k0 = v; ws = w; }
            }
            float wx = s_wx[ws], wy = s_wy[ws], wz = s_wz[ws];
            unsigned long long xy = ((unsigned long long)__float_as_uint(wy) << 32) |
                                    (unsigned long long)__float_as_uint(wx);
            unsigned long long zz = (unsigned long long)__float_as_uint(wz);
            unsigned loc = buf ? loc_b1 : loc_b0;
            unsigned pbase = mapa_u32(loc, t);
            st_cl_u64(pbase,      k0);
            st_cl_u64(pbase + 8,  xy);
            st_cl_u64(pbase + 16, zz);
        }
        cl_sync();   // release all 8 CTAs' stores, acquire everyone's

        // every thread redundantly picks the winner from local smem
        unsigned long long wmax = s_ex[buf][0][0];
        int w = 0;
#pragma unroll
        for (int c = 1; c < FPS_CTAS; c++) {
            unsigned long long v = s_ex[buf][c][0];
            if (v > wmax) { wmax = v; w = c; }
        }
        unsigned long long xy = s_ex[buf][w][1];
        lx = __uint_as_float((unsigned)(xy & 0xFFFFFFFFull));
        ly = __uint_as_float((unsigned)(xy >> 32));
        lz = __uint_as_float((unsigned)(s_ex[buf][w][2] & 0xFFFFFFFFull));
        if (rank == 0 && t == 0)
            g_fps[b * S + step] = (int)(0xFFFFFFFFu - (unsigned)(wmax & 0xFFFFFFFFull));
    }
    cl_sync();   // no CTA exits while peers may still address its smem
}

// ---------------- K2: ball query + gather + max + LayerNorms + out0 ----------------
__global__ void __launch_bounds__(256) k_group(
    const float* __restrict__ x, const float* __restrict__ iff,
    const float* __restrict__ gq, const float* __restrict__ bq,
    const float* __restrict__ gk, const float* __restrict__ bk,
    float* __restrict__ out0)
{
    int blk = blockIdx.x;
    int b = blk >> 6, s = blk & 63;
    int tid = threadIdx.x;

    __shared__ int   s_nidx[NS];
    __shared__ int   s_sidx;
    __shared__ float s_cx, s_cy, s_cz;
    __shared__ float s_red[32];
    __shared__ float s_stats[4];

    if (tid == 0) {
        int si = g_fps[b * S + s];
        s_sidx = si;
        float4 c = g_coor4[b * N + si];
        s_cx = c.x; s_cy = c.y; s_cz = c.z;
    }
    __syncthreads();

    if (tid < 32) {
        int lane = tid;
        float cx = s_cx, cy = s_cy, cz = s_cz;
        const float4* __restrict__ cp = g_coor4 + b * N;
        int found = 0;
        for (int base = 0; base < N && found < NS; base += 32) {
            float4 c = cp[base + lane];
            float dx = cx - c.x, dy = cy - c.y, dz = cz - c.z;
            float d2 = __fadd_rn(__fadd_rn(__fmul_rn(dx, dx), __fmul_rn(dy, dy)),
                                 __fmul_rn(dz, dz));
            bool v = d2 < 16.0f;
            unsigned m = __ballot_sync(0xffffffffu, v);
            int take = min(NS - found, __popc(m));
            int rank = __popc(m & ((1u << lane) - 1u));
            if (v && rank < take) s_nidx[found + rank] = base + lane;
            found += take;
        }
        __syncwarp();
        if (lane == 0) {
            int f0 = s_nidx[0];
            for (int j = found; j < NS; j++) s_nidx[j] = f0;
        }
    }
    __syncthreads();

    int c = tid;
    const float* __restrict__ xb = x + (size_t)b * N * DIM;
    int sidx = s_sidx;
    float sx = xb[(size_t)sidx * DIM + c];
    float gx = -FLT_MAX;
    int nidx[NS];
#pragma unroll
    for (int j = 0; j < NS; j++) nidx[j] = s_nidx[j];
#pragma unroll
    for (int j = 0; j < NS; j++)
        gx = fmaxf(gx, xb[(size_t)nidx[j] * DIM + c]);

    float x2 = gx - sx;
    out0[(size_t)(b * S + s) * DIM + c] = sx + x2;

    float v0 = sx, v1 = sx * sx, v2 = x2, v3 = x2 * x2;
#pragma unroll
    for (int o = 16; o; o >>= 1) {
        v0 += __shfl_down_sync(0xffffffffu, v0, o);
        v1 += __shfl_down_sync(0xffffffffu, v1, o);
        v2 += __shfl_down_sync(0xffffffffu, v2, o);
        v3 += __shfl_down_sync(0xffffffffu, v3, o);
    }
    int wid = tid >> 5;
    if ((tid & 31) == 0) {
        s_red[wid]      = v0;
        s_red[8 + wid]  = v1;
        s_red[16 + wid] = v2;
        s_red[24 + wid] = v3;
    }
    __syncthreads();
    if (tid == 0) {
        float t0 = 0, t1 = 0, t2 = 0, t3 = 0;
#pragma unroll
        for (int i = 0; i < 8; i++) {
            t0 += s_red[i]; t1 += s_red[8 + i]; t2 += s_red[16 + i]; t3 += s_red[24 + i];
        }
        float mk = t0 * (1.0f / DIM);
        float vk = t1 * (1.0f / DIM) - mk * mk;
        float mq = t2 * (1.0f / DIM);
        float vq = t3 * (1.0f / DIM) - mq * mq;
        s_stats[0] = mk;
        s_stats[1] = rsqrtf(vk + 1e-5f);
        s_stats[2] = mq;
        s_stats[3] = rsqrtf(vq + 1e-5f);
    }
    __syncthreads();

    float nk = (sx - s_stats[0]) * s_stats[1] * gk[c] + bk[c];
    float nq = (x2 - s_stats[2]) * s_stats[3] * gq[c] + bq[c];
    g_nk[(b * S + s) * DIM + c] = nk;
    g_nq[(b * S + s) * DIM + c] = nq;

    if (tid < 3) {
        float cen = (tid == 0) ? s_cx : (tid == 1) ? s_cy : s_cz;
        float acc = 0.f, acci = 0.f;
#pragma unroll
        for (int j = 0; j < NS; j++) {
            int p = nidx[j];
            float4 c4 = g_coor4[b * N + p];
            float comp = (tid == 0) ? c4.x : (tid == 1) ? c4.y : c4.z;
            acc  += (comp - cen);
            acci += iff[((size_t)b * N + p) * 3 + tid];
        }
        int o = (b * S + s) * 3 + tid;
        g_dc[o]  = acc * 0.125f;
        g_dif[o] = acci * 0.125f;
        g_sc[o]  = cen;
        g_sif[o] = iff[((size_t)b * N + sidx) * 3 + tid];
    }
}

// ---------------- K3a: Mt[e,d] = sum_c Wk[c,e] * Wq[c,d]  (256x256x256) ----------
__global__ void __launch_bounds__(256) k_wm(const float* __restrict__ Wq,
                                            const float* __restrict__ Wk)
{
    __shared__ float As[32][68];   // Wq chunk [cc][dd]
    __shared__ float Bs[32][68];   // Wk chunk [cc][ee]
    int tid = threadIdx.x;
    int d0 = blockIdx.x * 64;
    int e0 = blockIdx.y * 64;
    int tr = tid >> 4, tc = tid & 15;

    float acc[4][4] = {};
    for (int c0 = 0; c0 < 256; c0 += 32) {
        __syncthreads();
#pragma unroll
        for (int l = 0; l < 2; l++) {
            int idx = tid + l * 256;
            int cc = idx >> 4;
            int dq = idx & 15;
            *(float4*)&As[cc][dq * 4] = *(const float4*)&Wq[(c0 + cc) * 256 + d0 + dq * 4];
            *(float4*)&Bs[cc][dq * 4] = *(const float4*)&Wk[(c0 + cc) * 256 + e0 + dq * 4];
        }
        __syncthreads();
#pragma unroll
        for (int kk = 0; kk < 32; kk++) {
            float4 a4 = *(float4*)&Bs[kk][tr * 4];   // e
            float4 b4 = *(float4*)&As[kk][tc * 4];   // d
            float av[4] = {a4.x, a4.y, a4.z, a4.w};
            float bv[4] = {b4.x, b4.y, b4.z, b4.w};
#pragma unroll
            for (int i = 0; i < 4; i++)
#pragma unroll
                for (int j = 0; j < 4; j++)
                    acc[i][j] += av[i] * bv[j];
        }
    }
#pragma unroll
    for (int i = 0; i < 4; i++)
#pragma unroll
        for (int j = 0; j < 4; j++)
            g_m[(e0 + tr * 4 + i) * 256 + d0 + tc * 4 + j] = acc[i][j];
}

// ---------------- K3b: fused attn GEMM — per (b, e-slice):
//   P[64][64]   = nq[b] @ Mt[e0:e0+64]^T          (K = 256)
//   lsp[ks][b]  = P @ nk[b][:, e0:e0+64]^T        (K = 64)
// No qm intermediate in global memory.
__global__ void __launch_bounds__(256) k_attn() {
    int b = blockIdx.x, ks = blockIdx.y;
    int e0 = ks * 64;

    __shared__ float smAB[64][68];   // stage1: [0..31]=As(nq), [32..63]=Bs(Mt); stage2: Ns(nk^T)
    __shared__ float Ps[64][68];     // P transposed: Ps[e][i]

    int tid = threadIdx.x;
    int tr = tid >> 4, tc = tid & 15;
    int r0 = tid >> 3, kq0 = tid & 7;   // r0: 0..31, kq0: 0..7
    int r1 = r0 + 32;

    // ---- stage 1: P = nq[b] @ MtSlice^T (64x64x256) ----
    float acc[4][4] = {};
    for (int k0 = 0; k0 < 256; k0 += 32) {
        __syncthreads();
        // load As rows (nq) and Bs rows (Mt slice): 64 rows x 32 k each
        {
            float4 fa0 = *(const float4*)&g_nq[(size_t)(b * 64 + r0) * 256 + k0 + kq0 * 4];
            float4 fb0 = *(const float4*)&g_m[(size_t)(e0 + r0) * 256 + k0 + kq0 * 4];
            float4 fa1 = *(const float4*)&g_nq[(size_t)(b * 64 + r1) * 256 + k0 + kq0 * 4];
            float4 fb1 = *(const float4*)&g_m[(size_t)(e0 + r1) * 256 + k0 + kq0 * 4];
            smAB[kq0 * 4 + 0][r0] = fa0.x; smAB[kq0 * 4 + 1][r0] = fa0.y;
            smAB[kq0 * 4 + 2][r0] = fa0.z; smAB[kq0 * 4 + 3][r0] = fa0.w;
            smAB[32 + kq0 * 4 + 0][r0] = fb0.x; smAB[32 + kq0 * 4 + 1][r0] = fb0.y;
            smAB[32 + kq0 * 4 + 2][r0] = fb0.z; smAB[32 + kq0 * 4 + 3][r0] = fb0.w;
            smAB[kq0 * 4 + 0][r1] = fa1.x; smAB[kq0 * 4 + 1][r1] = fa1.y;
            smAB[kq0 * 4 + 2][r1] = fa1.z; smAB[kq0 * 4 + 3][r1] = fa1.w;
            smAB[32 + kq0 * 4 + 0][r1] = fb1.x; smAB[32 + kq0 * 4 + 1][r1] = fb1.y;
            smAB[32 + kq0 * 4 + 2][r1] = fb1.z; smAB[32 + kq0 * 4 + 3][r1] = fb1.w;
        }
        __syncthreads();
#pragma unroll
        for (int kk = 0; kk < 32; kk++) {
            float4 a4 = *(float4*)&smAB[kk][tr * 4];        // nq rows i
            float4 b4 = *(float4*)&smAB[32 + kk][tc * 4];   // Mt rows e
            float av[4] = {a4.x, a4.y, a4.z, a4.w};
            float bv[4] = {b4.x, b4.y, b4.z, b4.w};
#pragma unroll
            for (int i = 0; i < 4; i++)
#pragma unroll
                for (int j = 0; j < 4; j++)
                    acc[i][j] += av[i] * bv[j];
        }
    }
    // store P transposed: Ps[e][i] = P[i][e]
#pragma unroll
    for (int i = 0; i < 4; i++)
#pragma unroll
        for (int j = 0; j < 4; j++)
            Ps[tc * 4 + j][tr * 4 + i] = acc[i][j];
    __syncthreads();   // all stage-1 smAB reads + Ps writes complete

    // ---- stage 2: lsp = P @ nkSlice^T (64x64x64); Ns[ee][j] = nk[b][j][e0+ee] ----
#pragma unroll
    for (int l = 0; l < 4; l++) {
        int idx = tid + l * 256;          // 0..1023 -> 1024 float4
        int j  = idx >> 4;                // row 0..63
        int q  = idx & 15;                // float4 within row
        float4 f = *(const float4*)&g_nk[(size_t)(b * 64 + j) * 256 + e0 + q * 4];
        smAB[q * 4 + 0][j] = f.x; smAB[q * 4 + 1][j] = f.y;
        smAB[q * 4 + 2][j] = f.z; smAB[q * 4 + 3][j] = f.w;
    }
    __syncthreads();

    float acc2[4][4] = {};
#pragma unroll
    for (int kk = 0; kk < 64; kk++) {
        float4 a4 = *(float4*)&Ps[kk][tr * 4];     // P^T: [e][i]
        float4 b4 = *(float4*)&smAB[kk][tc * 4];   // nk^T: [e][j]
        float av[4] = {a4.x, a4.y, a4.z, a4.w};
        float bv[4] = {b4.x, b4.y, b4.z, b4.w};
#pragma unroll
        for (int i = 0; i < 4; i++)
#pragma unroll
            for (int j = 0; j < 4; j++)
                acc2[i][j] += av[i] * bv[j];
    }
    float* __restrict__ O = g_lsp[ks] + b * S * S;
#pragma unroll
    for (int i = 0; i < 4; i++)
#pragma unroll
        for (int j = 0; j < 4; j++)
            O[(tr * 4 + i) * S + tc * 4 + j] = acc2[i][j];
}

// ---------------- K4b: sum partial logits + softmax + attn@v + residuals ----------------
__global__ void __launch_bounds__(192) k_out(float* __restrict__ out) {
    int b = blockIdx.x;
    int tid = threadIdx.x;
    __shared__ float vc[192];
    __shared__ float vi[192];

    if (tid < 192) {
        int l = tid;
        int src = b * 192 + (l & 63) * 3 + (l >> 6);
        vc[tid] = g_dc[src];
        vi[tid] = g_dif[src];
    }
    __syncthreads();

    if (tid < S) {
        const float* __restrict__ l0 = g_lsp[0] + b * S * S + tid * S;
        const float* __restrict__ l1 = g_lsp[1] + b * S * S + tid * S;
        const float* __restrict__ l2 = g_lsp[2] + b * S * S + tid * S;
        const float* __restrict__ l3 = g_lsp[3] + b * S * S + tid * S;
        float lv[S];
        float mx = -FLT_MAX;
#pragma unroll
        for (int m = 0; m < S; m++) {
            lv[m] = (l0[m] + l1[m]) + (l2[m] + l3[m]);
            mx = fmaxf(mx, lv[m]);
        }
        float sum = 0.f;
        float a0 = 0, a1 = 0, a2 = 0, c0 = 0, c1 = 0, c2 = 0;
#pragma unroll
        for (int m = 0; m < S; m++) {
            float w = expf(lv[m] - mx);
            sum += w;
            a0 += w * vc[m * 3 + 0]; a1 += w * vc[m * 3 + 1]; a2 += w * vc[m * 3 + 2];
            c0 += w * vi[m * 3 + 0]; c1 += w * vi[m * 3 + 1]; c2 += w * vi[m * 3 + 2];
        }
        float inv = 1.0f / sum;
        int o = (b * S + tid) * 3;
        float* out1 = out + (size_t)B * S * DIM;
        float* out2 = out1 + B * S * 3;
        out1[o + 0] = g_sc[o + 0] + a0 * inv;
        out1[o + 1] = g_sc[o + 1] + a1 * inv;
        out1[o + 2] = g_sc[o + 2] + a2 * inv;
        out2[o + 0] = g_sif[o + 0] + c0 * inv;
        out2[o + 1] = g_sif[o + 1] + c1 * inv;
        out2[o + 2] = g_sif[o + 2] + c2 * inv;
    }
}

// ---------------- launch ----------------
extern "C" void kernel_launch(void* const* d_in, const int* in_sizes, int n_in,
                              void* d_out, int out_size)
{
    const float* iff  = (const float*)d_in[0];
    const float* x    = (const float*)d_in[1];
    const float* coor = (const float*)d_in[2];
    const float* Wq   = (const float*)d_in[3];
    const float* Wk   = (const float*)d_in[4];
    const float* gq   = (const float*)d_in[5];
    const float* bq   = (const float*)d_in[6];
    const float* gk   = (const float*)d_in[7];
    const float* bk   = (const float*)d_in[8];
    float* out = (float*)d_out;

    k_wm<<<dim3(4, 4), 256>>>(Wq, Wk);          // independent of FPS region
    k_fps<<<B * FPS_CTAS, FPS_THR>>>(coor);
    k_group<<<B * S, 256>>>(x, iff, gq, bq, gk, bk, out);
    k_attn<<<dim3(16, 4), 256>>>();
    k_out<<<B, 192>>>(out);
}

// round 17
// speedup vs baseline: 1.5064x; 1.0339x over previous
#include <cuda_runtime.h>
#include <math.h>
#include <float.h>

#define B   16
#define N   32768
#define DIM 256
#define S   64
#define NS  8

#define FPS_CTAS   8            // CTAs per batch (cluster size)
#define FPS_THR    256          // threads per CTA
#define PPT        16           // points per thread (4096 / 256)

// ---------------- scratch (static device globals; no allocation) ----------------
__device__ float4 g_coor4[B * N];            // packed coords — 8MB (written by k_fps)
__device__ int    g_fps[B * S];
__device__ float  g_nq[B * S * DIM];
__device__ float  g_nk[B * S * DIM];
__device__ float  g_m[DIM * DIM];            // Mt[e][d] = sum_c Wk[c,e] Wq[c,d]
__device__ float  g_lsp[4][B * S * S];       // split-e partial logits
__device__ float  g_dc[B * S * 3];
__device__ float  g_dif[B * S * 3];
__device__ float  g_sc[B * S * 3];
__device__ float  g_sif[B * S * 3];

// ---------------- cluster helpers ----------------
__device__ __forceinline__ unsigned cl_rank() {
    unsigned r; asm("mov.u32 %0, %%cluster_ctarank;" : "=r"(r)); return r;
}
__device__ __forceinline__ void cl_sync() {
    asm volatile("barrier.cluster.arrive.aligned;" ::: "memory");
    asm volatile("barrier.cluster.wait.aligned;"   ::: "memory");
}
__device__ __forceinline__ unsigned smem_u32(const void* p) {
    unsigned a;
    asm("{ .reg .u64 t; cvta.to.shared.u64 t, %1; cvt.u32.u64 %0, t; }" : "=r"(a) : "l"(p));
    return a;
}
__device__ __forceinline__ unsigned mapa_u32(unsigned saddr, unsigned rank) {
    unsigned rem;
    asm volatile("mapa.shared::cluster.u32 %0, %1, %2;" : "=r"(rem) : "r"(saddr), "r"(rank));
    return rem;
}
__device__ __forceinline__ void st_cl_u64(unsigned addr, unsigned long long v) {
    asm volatile("st.shared::cluster.b64 [%0], %1;" :: "r"(addr), "l"(v) : "memory");
}

// pack (dist, idx) so u64-max == (max dist, tie -> min idx). dist >= 0.
__device__ __forceinline__ unsigned long long pack_cand(float v, int idx) {
    return ((unsigned long long)__float_as_uint(v) << 32) |
           (unsigned long long)(0xFFFFFFFFu - (unsigned)idx);
}

// ---------------- K1: FPS (pack fused) — cluster of 8 CTAs, cluster.sync exchange --
// EXACT R12 configuration (256 thr x 16 ppt) — proven 131.8us; frozen.
__global__ void __launch_bounds__(FPS_THR, 1) __cluster_dims__(FPS_CTAS, 1, 1)
k_fps(const float* __restrict__ coor) {
    int b = blockIdx.x / FPS_CTAS;
    unsigned rank = cl_rank();
    int t = threadIdx.x;
    int base = rank * (N / FPS_CTAS);
    const float* __restrict__ cb = coor + (size_t)b * N * 3;

    float px[PPT], py[PPT], pz[PPT], dists[PPT];
#pragma unroll
    for (int k = 0; k < PPT; k++) {
        int p = base + t + k * FPS_THR;
        float x = cb[3 * p + 0];
        float y = cb[3 * p + 1];
        float z = cb[3 * p + 2];
        px[k] = x; py[k] = y; pz[k] = z;
        dists[k] = 1e10f;
        float4 v; v.x = x; v.y = y; v.z = z; v.w = 0.f;
        g_coor4[b * N + p] = v;
    }

    __shared__ unsigned long long s_ex[2][FPS_CTAS][3];   // key, xy, z
    __shared__ unsigned long long s_wk[FPS_THR / 32];
    __shared__ float s_wx[FPS_THR / 32], s_wy[FPS_THR / 32], s_wz[FPS_THR / 32];

    if (rank == 0 && t == 0) g_fps[b * S] = 0;

    float lx = cb[0], ly = cb[1], lz = cb[2];

    unsigned loc_b0 = smem_u32(&s_ex[0][rank][0]);
    unsigned loc_b1 = smem_u32(&s_ex[1][rank][0]);

    for (int step = 1; step < S; step++) {
        int buf = step & 1;
        float best = -1.0f;
#pragma unroll
        for (int k = 0; k < PPT; k++) {
            float dx = px[k] - lx, dy = py[k] - ly, dz = pz[k] - lz;
            float d = __fadd_rn(__fadd_rn(__fmul_rn(dx, dx), __fmul_rn(dy, dy)),
                                __fmul_rn(dz, dz));
            float nd = fminf(dists[k], d);
            dists[k] = nd;
            best = fmaxf(best, nd);
        }
        // resolve: descending k, unconditional overwrite => lowest idx on ties
        int besti = base + t;
        float bx = px[0], by = py[0], bz = pz[0];
#pragma unroll
        for (int k = PPT - 1; k >= 0; k--) {
            if (dists[k] == best) {
                besti = base + t + k * FPS_THR;
                bx = px[k]; by = py[k]; bz = pz[k];
            }
        }
        unsigned long long key = pack_cand(best, besti);

        // warp stage: butterfly max on key; unique winner lane writes
        unsigned long long wkey = key;
#pragma unroll
        for (int o = 16; o; o >>= 1) {
            unsigned long long ok = __shfl_xor_sync(0xffffffffu, wkey, o);
            if (ok > wkey) wkey = ok;
        }
        if (key == wkey) {
            int w = t >> 5;
            s_wk[w] = wkey; s_wx[w] = bx; s_wy[w] = by; s_wz[w] = bz;
        }
        __syncthreads();

        // block stage: threads t<8 each scan the warp winners; thread t ships to CTA t
        if (t < FPS_CTAS) {
            unsigned long long k0 = s_wk[0]; int ws = 0;
#pragma unroll
            for (int w = 1; w < FPS_THR / 32; w++) {
                unsigned long long v = s_wk[w];
                if (v > k0) { k0 = v; ws = w; }
            }
            float wx = s_wx[ws], wy = s_wy[ws], wz = s_wz[ws];
            unsigned long long xy = ((unsigned long long)__float_as_uint(wy) << 32) |
                                    (unsigned long long)__float_as_uint(wx);
            unsigned long long zz = (unsigned long long)__float_as_uint(wz);
            unsigned loc = buf ? loc_b1 : loc_b0;
            unsigned pbase = mapa_u32(loc, t);
            st_cl_u64(pbase,      k0);
            st_cl_u64(pbase + 8,  xy);
            st_cl_u64(pbase + 16, zz);
        }
        cl_sync();   // release all 8 CTAs' stores, acquire everyone's

        // every thread redundantly picks the winner from local smem
        unsigned long long wmax = s_ex[buf][0][0];
        int w = 0;
#pragma unroll
        for (int c = 1; c < FPS_CTAS; c++) {
            unsigned long long v = s_ex[buf][c][0];
            if (v > wmax) { wmax = v; w = c; }
        }
        unsigned long long xy = s_ex[buf][w][1];
        lx = __uint_as_float((unsigned)(xy & 0xFFFFFFFFull));
        ly = __uint_as_float((unsigned)(xy >> 32));
        lz = __uint_as_float((unsigned)(s_ex[buf][w][2] & 0xFFFFFFFFull));
        if (rank == 0 && t == 0)
            g_fps[b * S + step] = (int)(0xFFFFFFFFu - (unsigned)(wmax & 0xFFFFFFFFull));
    }
    cl_sync();   // no CTA exits while peers may still address its smem
}

// ---------------- K2: ball query + gather + max + LayerNorms + out0 ----------------
__global__ void __launch_bounds__(256) k_group(
    const float* __restrict__ x, const float* __restrict__ iff,
    const float* __restrict__ gq, const float* __restrict__ bq,
    const float* __restrict__ gk, const float* __restrict__ bk,
    float* __restrict__ out0)
{
    int blk = blockIdx.x;
    int b = blk >> 6, s = blk & 63;
    int tid = threadIdx.x;

    __shared__ int   s_nidx[NS];
    __shared__ int   s_sidx;
    __shared__ float s_cx, s_cy, s_cz;
    __shared__ float s_red[32];
    __shared__ float s_stats[4];

    if (tid == 0) {
        int si = g_fps[b * S + s];
        s_sidx = si;
        float4 c = g_coor4[b * N + si];
        s_cx = c.x; s_cy = c.y; s_cz = c.z;
    }
    __syncthreads();

    if (tid < 32) {
        int lane = tid;
        float cx = s_cx, cy = s_cy, cz = s_cz;
        const float4* __restrict__ cp = g_coor4 + b * N;
        int found = 0;
        for (int base = 0; base < N && found < NS; base += 32) {
            float4 c = cp[base + lane];
            float dx = cx - c.x, dy = cy - c.y, dz = cz - c.z;
            float d2 = __fadd_rn(__fadd_rn(__fmul_rn(dx, dx), __fmul_rn(dy, dy)),
                                 __fmul_rn(dz, dz));
            bool v = d2 < 16.0f;
            unsigned m = __ballot_sync(0xffffffffu, v);
            int take = min(NS - found, __popc(m));
            int rank = __popc(m & ((1u << lane) - 1u));
            if (v && rank < take) s_nidx[found + rank] = base + lane;
            found += take;
        }
        __syncwarp();
        if (lane == 0) {
            int f0 = s_nidx[0];
            for (int j = found; j < NS; j++) s_nidx[j] = f0;
        }
    }
    __syncthreads();

    int c = tid;
    const float* __restrict__ xb = x + (size_t)b * N * DIM;
    int sidx = s_sidx;
    float sx = xb[(size_t)sidx * DIM + c];
    float gx = -FLT_MAX;
    int nidx[NS];
#pragma unroll
    for (int j = 0; j < NS; j++) nidx[j] = s_nidx[j];
#pragma unroll
    for (int j = 0; j < NS; j++)
        gx = fmaxf(gx, xb[(size_t)nidx[j] * DIM + c]);

    float x2 = gx - sx;
    out0[(size_t)(b * S + s) * DIM + c] = sx + x2;

    float v0 = sx, v1 = sx * sx, v2 = x2, v3 = x2 * x2;
#pragma unroll
    for (int o = 16; o; o >>= 1) {
        v0 += __shfl_down_sync(0xffffffffu, v0, o);
        v1 += __shfl_down_sync(0xffffffffu, v1, o);
        v2 += __shfl_down_sync(0xffffffffu, v2, o);
        v3 += __shfl_down_sync(0xffffffffu, v3, o);
    }
    int wid = tid >> 5;
    if ((tid & 31) == 0) {
        s_red[wid]      = v0;
        s_red[8 + wid]  = v1;
        s_red[16 + wid] = v2;
        s_red[24 + wid] = v3;
    }
    __syncthreads();
    if (tid == 0) {
        float t0 = 0, t1 = 0, t2 = 0, t3 = 0;
#pragma unroll
        for (int i = 0; i < 8; i++) {
            t0 += s_red[i]; t1 += s_red[8 + i]; t2 += s_red[16 + i]; t3 += s_red[24 + i];
        }
        float mk = t0 * (1.0f / DIM);
        float vk = t1 * (1.0f / DIM) - mk * mk;
        float mq = t2 * (1.0f / DIM);
        float vq = t3 * (1.0f / DIM) - mq * mq;
        s_stats[0] = mk;
        s_stats[1] = rsqrtf(vk + 1e-5f);
        s_stats[2] = mq;
        s_stats[3] = rsqrtf(vq + 1e-5f);
    }
    __syncthreads();

    float nk = (sx - s_stats[0]) * s_stats[1] * gk[c] + bk[c];
    float nq = (x2 - s_stats[2]) * s_stats[3] * gq[c] + bq[c];
    g_nk[(b * S + s) * DIM + c] = nk;
    g_nq[(b * S + s) * DIM + c] = nq;

    if (tid < 3) {
        float cen = (tid == 0) ? s_cx : (tid == 1) ? s_cy : s_cz;
        float acc = 0.f, acci = 0.f;
#pragma unroll
        for (int j = 0; j < NS; j++) {
            int p = nidx[j];
            float4 c4 = g_coor4[b * N + p];
            float comp = (tid == 0) ? c4.x : (tid == 1) ? c4.y : c4.z;
            acc  += (comp - cen);
            acci += iff[((size_t)b * N + p) * 3 + tid];
        }
        int o = (b * S + s) * 3 + tid;
        g_dc[o]  = acc * 0.125f;
        g_dif[o] = acci * 0.125f;
        g_sc[o]  = cen;
        g_sif[o] = iff[((size_t)b * N + sidx) * 3 + tid];
    }
}

// ---------------- K3a: Mt[e,d] = sum_c Wk[c,e] * Wq[c,d]  (256x256x256) ----------
__global__ void __launch_bounds__(256) k_wm(const float* __restrict__ Wq,
                                            const float* __restrict__ Wk)
{
    __shared__ float As[32][68];   // Wq chunk [cc][dd]
    __shared__ float Bs[32][68];   // Wk chunk [cc][ee]
    int tid = threadIdx.x;
    int d0 = blockIdx.x * 64;
    int e0 = blockIdx.y * 64;
    int tr = tid >> 4, tc = tid & 15;

    float acc[4][4] = {};
    for (int c0 = 0; c0 < 256; c0 += 32) {
        __syncthreads();
#pragma unroll
        for (int l = 0; l < 2; l++) {
            int idx = tid + l * 256;
            int cc = idx >> 4;
            int dq = idx & 15;
            *(float4*)&As[cc][dq * 4] = *(const float4*)&Wq[(c0 + cc) * 256 + d0 + dq * 4];
            *(float4*)&Bs[cc][dq * 4] = *(const float4*)&Wk[(c0 + cc) * 256 + e0 + dq * 4];
        }
        __syncthreads();
#pragma unroll
        for (int kk = 0; kk < 32; kk++) {
            float4 a4 = *(float4*)&Bs[kk][tr * 4];   // e
            float4 b4 = *(float4*)&As[kk][tc * 4];   // d
            float av[4] = {a4.x, a4.y, a4.z, a4.w};
            float bv[4] = {b4.x, b4.y, b4.z, b4.w};
#pragma unroll
            for (int i = 0; i < 4; i++)
#pragma unroll
                for (int j = 0; j < 4; j++)
                    acc[i][j] += av[i] * bv[j];
        }
    }
#pragma unroll
    for (int i = 0; i < 4; i++)
#pragma unroll
        for (int j = 0; j < 4; j++)
            g_m[(e0 + tr * 4 + i) * 256 + d0 + tc * 4 + j] = acc[i][j];
}

// ---------------- K3b: fused attn GEMM v2 — per (b, e-slice, i-half):
//   P[32][64]        = nq[b][i0:i0+32] @ Mt[e0:e0+64]^T   (K = 256, reg-prefetch)
//   lsp[ks][b][i0:+32] = P @ nk[b][:, e0:e0+64]^T         (K = 64)
// 128 CTAs (single wave), no qm intermediate in global memory.
__global__ void __launch_bounds__(256) k_attn() {
    int b = blockIdx.x, ks = blockIdx.y, ih = blockIdx.z;
    int e0 = ks * 64;
    int i0 = ih * 32;

    __shared__ float As[32][36];   // nq:  [k][i]   (32 rows i)
    __shared__ float Bs[32][68];   // Mt:  [k][e]   (64 rows e)
    __shared__ float Ps[64][36];   // P^T: [e][i]
    __shared__ float Ns[64][68];   // nk^T:[e][j]

    int tid = threadIdx.x;
    int tr = tid >> 4, tc = tid & 15;     // tr: i-pair 0..15, tc: e/j-quad 0..15
    int ra = tid >> 3, kq = tid & 7;      // ra 0..31
    int rb = ra + 32;

    // ---- stage 1 with register prefetch ----
    float4 fa, fb0, fb1;
    fa  = *(const float4*)&g_nq[(size_t)(b * 64 + i0 + ra) * 256 + kq * 4];
    fb0 = *(const float4*)&g_m[(size_t)(e0 + ra) * 256 + kq * 4];
    fb1 = *(const float4*)&g_m[(size_t)(e0 + rb) * 256 + kq * 4];

    float acc[2][4] = {};
#pragma unroll
    for (int kt = 0; kt < 8; kt++) {
        __syncthreads();
        As[kq * 4 + 0][ra] = fa.x;  As[kq * 4 + 1][ra] = fa.y;
        As[kq * 4 + 2][ra] = fa.z;  As[kq * 4 + 3][ra] = fa.w;
        Bs[kq * 4 + 0][ra] = fb0.x; Bs[kq * 4 + 1][ra] = fb0.y;
        Bs[kq * 4 + 2][ra] = fb0.z; Bs[kq * 4 + 3][ra] = fb0.w;
        Bs[kq * 4 + 0][rb] = fb1.x; Bs[kq * 4 + 1][rb] = fb1.y;
        Bs[kq * 4 + 2][rb] = fb1.z; Bs[kq * 4 + 3][rb] = fb1.w;
        __syncthreads();
        if (kt < 7) {
            int ko = (kt + 1) * 32;
            fa  = *(const float4*)&g_nq[(size_t)(b * 64 + i0 + ra) * 256 + ko + kq * 4];
            fb0 = *(const float4*)&g_m[(size_t)(e0 + ra) * 256 + ko + kq * 4];
            fb1 = *(const float4*)&g_m[(size_t)(e0 + rb) * 256 + ko + kq * 4];
        }
#pragma unroll
        for (int kk = 0; kk < 32; kk++) {
            float a0 = As[kk][tr * 2 + 0];
            float a1 = As[kk][tr * 2 + 1];
            float4 b4 = *(float4*)&Bs[kk][tc * 4];
            acc[0][0] += a0 * b4.x; acc[0][1] += a0 * b4.y;
            acc[0][2] += a0 * b4.z; acc[0][3] += a0 * b4.w;
            acc[1][0] += a1 * b4.x; acc[1][1] += a1 * b4.y;
            acc[1][2] += a1 * b4.z; acc[1][3] += a1 * b4.w;
        }
    }
    // write P transposed: Ps[e][i] = P[i][e]
#pragma unroll
    for (int i = 0; i < 2; i++)
#pragma unroll
        for (int j = 0; j < 4; j++)
            Ps[tc * 4 + j][tr * 2 + i] = acc[i][j];

    // ---- load Ns (separate smem; overlaps Ps writes) ----
#pragma unroll
    for (int l = 0; l < 4; l++) {
        int idx = tid + l * 256;            // 1024 float4s
        int j = idx >> 4;                   // 0..63
        int q = idx & 15;                   // 0..15
        float4 f = *(const float4*)&g_nk[(size_t)(b * 64 + j) * 256 + e0 + q * 4];
        Ns[q * 4 + 0][j] = f.x; Ns[q * 4 + 1][j] = f.y;
        Ns[q * 4 + 2][j] = f.z; Ns[q * 4 + 3][j] = f.w;
    }
    __syncthreads();

    // ---- stage 2: lsp = P @ nkSlice^T (32x64x64) ----
    float acc2[2][4] = {};
#pragma unroll
    for (int kk = 0; kk < 64; kk++) {
        float a0 = Ps[kk][tr * 2 + 0];
        float a1 = Ps[kk][tr * 2 + 1];
        float4 b4 = *(float4*)&Ns[kk][tc * 4];
        acc2[0][0] += a0 * b4.x; acc2[0][1] += a0 * b4.y;
        acc2[0][2] += a0 * b4.z; acc2[0][3] += a0 * b4.w;
        acc2[1][0] += a1 * b4.x; acc2[1][1] += a1 * b4.y;
        acc2[1][2] += a1 * b4.z; acc2[1][3] += a1 * b4.w;
    }
    float* __restrict__ O = g_lsp[ks] + b * S * S;
#pragma unroll
    for (int i = 0; i < 2; i++)
#pragma unroll
        for (int j = 0; j < 4; j++)
            O[(i0 + tr * 2 + i) * S + tc * 4 + j] = acc2[i][j];
}

// ---------------- K4b: sum partial logits + softmax + attn@v + residuals ----------------
__global__ void __launch_bounds__(192) k_out(float* __restrict__ out) {
    int b = blockIdx.x;
    int tid = threadIdx.x;
    __shared__ float vc[192];
    __shared__ float vi[192];

    if (tid < 192) {
        int l = tid;
        int src = b * 192 + (l & 63) * 3 + (l >> 6);
        vc[tid] = g_dc[src];
        vi[tid] = g_dif[src];
    }
    __syncthreads();

    if (tid < S) {
        const float* __restrict__ l0 = g_lsp[0] + b * S * S + tid * S;
        const float* __restrict__ l1 = g_lsp[1] + b * S * S + tid * S;
        const float* __restrict__ l2 = g_lsp[2] + b * S * S + tid * S;
        const float* __restrict__ l3 = g_lsp[3] + b * S * S + tid * S;
        float lv[S];
        float mx = -FLT_MAX;
#pragma unroll
        for (int m = 0; m < S; m++) {
            lv[m] = (l0[m] + l1[m]) + (l2[m] + l3[m]);
            mx = fmaxf(mx, lv[m]);
        }
        float sum = 0.f;
        float a0 = 0, a1 = 0, a2 = 0, c0 = 0, c1 = 0, c2 = 0;
#pragma unroll
        for (int m = 0; m < S; m++) {
            float w = expf(lv[m] - mx);
            sum += w;
            a0 += w * vc[m * 3 + 0]; a1 += w * vc[m * 3 + 1]; a2 += w * vc[m * 3 + 2];
            c0 += w * vi[m * 3 + 0]; c1 += w * vi[m * 3 + 1]; c2 += w * vi[m * 3 + 2];
        }
        float inv = 1.0f / sum;
        int o = (b * S + tid) * 3;
        float* out1 = out + (size_t)B * S * DIM;
        float* out2 = out1 + B * S * 3;
        out1[o + 0] = g_sc[o + 0] + a0 * inv;
        out1[o + 1] = g_sc[o + 1] + a1 * inv;
        out1[o + 2] = g_sc[o + 2] + a2 * inv;
        out2[o + 0] = g_sif[o + 0] + c0 * inv;
        out2[o + 1] = g_sif[o + 1] + c1 * inv;
        out2[o + 2] = g_sif[o + 2] + c2 * inv;
    }
}

// ---------------- launch ----------------
extern "C" void kernel_launch(void* const* d_in, const int* in_sizes, int n_in,
                              void* d_out, int out_size)
{
    const float* iff  = (const float*)d_in[0];
    const float* x    = (const float*)d_in[1];
    const float* coor = (const float*)d_in[2];
    const float* Wq   = (const float*)d_in[3];
    const float* Wk   = (const float*)d_in[4];
    const float* gq   = (const float*)d_in[5];
    const float* bq   = (const float*)d_in[6];
    const float* gk   = (const float*)d_in[7];
    const float* bk   = (const float*)d_in[8];
    float* out = (float*)d_out;

    k_wm<<<dim3(4, 4), 256>>>(Wq, Wk);          // independent of FPS region
    k_fps<<<B * FPS_CTAS, FPS_THR>>>(coor);
    k_group<<<B * S, 256>>>(x, iff, gq, bq, gk, bk, out);
    k_attn<<<dim3(16, 4, 2), 256>>>();
    k_out<<<B, 192>>>(out);
}